// round 12
// baseline (speedup 1.0000x reference)
#include <cuda_runtime.h>
#include <math.h>

#define BB 8
#define LL 512
#define DD 128
#define UU 32
#define EPSF 1e-7f
#define NC 64            // 8-row chunks per batch
#define NSC 8            // superchunks of 64 rows per batch
#define GRID (BB*NC)     // 512 blocks

// scratch (no allocs allowed)
__device__ float g_qs[BB*LL];
__device__ float g_ks[BB*LL];
__device__ float g_ek[BB*LL];
__device__ float g_T8 [BB*NC*DD];       // 8-row sums of x
__device__ float g_T8e[BB*NC*DD];       // 8-row sums of ek*x
__device__ float g_SO0[BB*(NSC+1)*DD];  // exclusive superchunk offsets of x; [8]=total
__device__ float g_SO1[BB*(NSC+1)*DD];  // exclusive superchunk offsets of ek*x
__device__ float g_A[BB*LL];            // exp(qc-m)/Z
__device__ float g_E[BB*LL];            // exp(-m)/Z
__device__ unsigned g_cnt;              // grid barrier counter (reset each run)
__device__ unsigned g_done;             // end-of-kernel reset counter

struct SmemP1 {
    __align__(16) float swt[DD];
    __align__(16) float swx[DD];
    __align__(16) float srow[8*DD];
    float sek[8];
};
struct SmemP2 {
    float sks[LL];
    float scan[2][LL];
    float cmax[LL/16];
    float s8[2][NSC][DD];
    float sc_c;
};
union SmemU { SmemP1 p1; SmemP2 p2; };

// grid barrier: all GRID blocks resident (guaranteed by __launch_bounds__(256,4))
__device__ __forceinline__ void gbar(unsigned target) {
    __syncthreads();
    if (threadIdx.x == 0) {
        __threadfence();
        atomicAdd(&g_cnt, 1u);
        while (*(volatile unsigned*)&g_cnt < target) { }
        __threadfence();
    }
    __syncthreads();
}

__global__ __launch_bounds__(256, 4)
void fused(const float* __restrict__ x,
           const float* __restrict__ Wt, const float* __restrict__ Wx,
           const float* __restrict__ bh, const float* __restrict__ Wa,
           const float* __restrict__ ba, float* __restrict__ out) {
    __shared__ SmemU smem;
    int tid  = threadIdx.x;
    int blk  = blockIdx.x;

    // ===================== Phase 1: scalars + chunk sums =====================
    {
        SmemP1& S = smem.p1;
        int warp = tid >> 5;
        int lane = tid & 31;
        int token = blk * 8 + warp;                 // 8 consecutive rows, same batch

        // issue x load first (long latency, overlaps fold)
        const float4* xr = reinterpret_cast<const float4*>(x + (size_t)token * DD);
        float4 xv = xr[lane];
        reinterpret_cast<float4*>(S.srow)[warp*32 + lane] = xv;

        // register fold: ug = tid&7 fixed; row(i) = (tid + 256*i) >> 3
        {
            int ug = tid & 7;
            float4 wa = reinterpret_cast<const float4*>(Wa)[ug];
            const float4* Wt4 = reinterpret_cast<const float4*>(Wt);
            const float4* Wx4 = reinterpret_cast<const float4*>(Wx);
#pragma unroll
            for (int i = 0; i < 4; i++) {
                int idx = tid + i*256;
                int row = idx >> 3;
                float4 vt = __ldg(Wt4 + idx);
                float4 vx = __ldg(Wx4 + idx);
                float pt = vt.x*wa.x + vt.y*wa.y + vt.z*wa.z + vt.w*wa.w;
                float px = vx.x*wa.x + vx.y*wa.y + vx.z*wa.z + vx.w*wa.w;
#pragma unroll
                for (int o = 4; o; o >>= 1) {       // reduce across 8-lane row group
                    pt += __shfl_down_sync(0xFFFFFFFFu, pt, o, 8);
                    px += __shfl_down_sync(0xFFFFFFFFu, px, o, 8);
                }
                if (ug == 0) { S.swt[row] = pt; S.swx[row] = px; }
            }
        }
        __syncthreads();

        float4 wt = reinterpret_cast<const float4*>(S.swt)[lane];
        float4 wx = reinterpret_cast<const float4*>(S.swx)[lane];
        float q = xv.x*wt.x + xv.y*wt.y + xv.z*wt.z + xv.w*wt.w;
        float k = xv.x*wx.x + xv.y*wx.y + xv.z*wx.z + xv.w*wx.w;
#pragma unroll
        for (int o = 16; o; o >>= 1) {
            q += __shfl_down_sync(0xFFFFFFFFu, q, o);
            k += __shfl_down_sync(0xFFFFFFFFu, k, o);
        }
        if (lane == 0) {
            float e = expf(k);
            g_qs[token] = q;
            g_ks[token] = k;
            g_ek[token] = e;
            S.sek[warp] = e;
        }
        __syncthreads();

        if (tid < DD) {
            int d = tid;
            float s0 = 0.f, s1 = 0.f;
#pragma unroll
            for (int w = 0; w < 8; w++) {
                float v = S.srow[w*DD + d];
                s0 += v;
                s1 = fmaf(S.sek[w], v, s1);
            }
            size_t o = (size_t)blk * DD + d;
            g_T8 [o] = s0;
            g_T8e[o] = s1;
        }
    }

    gbar(GRID);

    // ===================== Phase 2: per-batch scan + scalars (blocks 0-7) ====
    if (blk < BB) {
        SmemP2& S = smem.p2;
        int b = blk;

#pragma unroll
        for (int e = 0; e < 2; e++) {
            int t = tid + e*256;
            S.sks[t]     = g_ks[b*LL + t];
            S.scan[0][t] = g_ek[b*LL + t];
        }
        if (tid == 0) {
            float c = __ldg(ba);
#pragma unroll
            for (int u = 0; u < UU; u++) c = fmaf(__ldg(bh + u), __ldg(Wa + u), c);
            S.sc_c = c;
        }
        __syncthreads();

        if (tid < LL/16) {
            float m = S.sks[tid*16];
#pragma unroll
            for (int i = 1; i < 16; i++) m = fmaxf(m, S.sks[tid*16 + i]);
            S.cmax[tid] = m;
        }

        // superchunk sums from T8: g in {0,1}, q stepped by 2
        {
            int g = tid >> 7, d = tid & (DD-1);
#pragma unroll
            for (int q = g; q < NSC; q += 2) {
                float a0 = 0.f, a1 = 0.f;
#pragma unroll
                for (int j = 0; j < 8; j++) {
                    a0 += g_T8 [(size_t)(b*NC + q*8 + j)*DD + d];
                    a1 += g_T8e[(size_t)(b*NC + q*8 + j)*DD + d];
                }
                S.s8[0][q][d] = a0;
                S.s8[1][q][d] = a1;
            }
        }

        // Hillis-Steele scan of 512 with 256 threads (2 elems/thread)
        int cur = 0;
#pragma unroll
        for (int off = 1; off < LL; off <<= 1) {
            __syncthreads();
#pragma unroll
            for (int e = 0; e < 2; e++) {
                int i = tid + e*256;
                float v = S.scan[cur][i];
                if (i >= off) v += S.scan[cur][i - off];
                S.scan[cur ^ 1][i] = v;
            }
            cur ^= 1;
        }
        __syncthreads();

        // exclusive superchunk offsets (incl. total at [8]) -> global
        if (tid < DD) {
            int d = tid;
            float r0 = 0.f, r1 = 0.f;
#pragma unroll
            for (int sc = 0; sc < NSC; sc++) {
                g_SO0[(size_t)(b*(NSC+1) + sc)*DD + d] = r0;
                g_SO1[(size_t)(b*(NSC+1) + sc)*DD + d] = r1;
                r0 += S.s8[0][sc][d];
                r1 += S.s8[1][sc][d];
            }
            g_SO0[(size_t)(b*(NSC+1) + NSC)*DD + d] = r0;
            g_SO1[(size_t)(b*(NSC+1) + NSC)*DD + d] = r1;
        }

        // per-query softmax scalars (2 queries/thread)
#pragma unroll
        for (int e = 0; e < 2; e++) {
            int t  = tid + e*256;
            int lo = max(0, t - 63);
            int hi = min(LL - 1, t + 64);
            int wc = hi - lo + 1;

            float wm = -INFINITY;
            int c0 = lo >> 4, c1 = hi >> 4;
            int e0 = (c0 + 1) << 4;
            for (int s = lo; s < e0; s++) wm = fmaxf(wm, S.sks[s]);
            for (int c = c0 + 1; c < c1; c++) wm = fmaxf(wm, S.cmax[c]);
            for (int s = c1 << 4; s <= hi; s++) wm = fmaxf(wm, S.sks[s]);

            float qc = g_qs[b*LL + t] + S.sc_c;
            float m  = fmaxf(0.f, qc + wm);     // masked entries score 0, always present
            float A  = expf(qc - m);
            float E  = expf(-m);
            float S1 = S.scan[cur][hi] - (lo > 0 ? S.scan[cur][lo-1] : 0.f);
            float Z  = A * S1 + E * (float)(LL - wc) + EPSF;
            float iv = 1.f / Z;
            g_A[b*LL + t] = A * iv;
            g_E[b*LL + t] = E * iv;
        }
    }

    gbar(2*GRID);

    // ===================== Phase 3: output (blocks 0-255, 16 queries each) ===
    if (blk < 256) {
        int b   = blk >> 5;
        int t0  = (blk & 31) * 16 + (tid >> 7) * 8;
        int d   = tid & (DD-1);

        bool lo_act = (t0 >= 64);
        bool hi_act = (t0 <= 440);
        float whi = hi_act ? 1.f : 0.f;
        float wlo = lo_act ? 1.f : 0.f;

        int jh = hi_act ? ((t0 >> 3) + 8) : NC;
        int jl = lo_act ? ((t0 >> 3) - 8) : 0;
        int sc_h = jh >> 3, r_h = jh & 7;
        int sc_l = jl >> 3, r_l = jl & 7;

        const float* xb  = x + (size_t)b * LL * DD;
        const float* ekb = g_ek + b*LL;
        size_t sobase = (size_t)b * (NSC+1) * DD;
        size_t t8base = (size_t)b * NC;

        float c0h = __ldg(g_SO0 + sobase + (size_t)sc_h*DD + d);
        float c1h = __ldg(g_SO1 + sobase + (size_t)sc_h*DD + d);
        float c0l = __ldg(g_SO0 + sobase + (size_t)sc_l*DD + d);
        float c1l = __ldg(g_SO1 + sobase + (size_t)sc_l*DD + d);
        float tot = __ldg(g_SO0 + sobase + (size_t)NSC*DD + d);

#pragma unroll
        for (int j = 0; j < 7; j++) {
            if (j < r_h) {
                c0h += __ldg(g_T8  + (size_t)(t8base + sc_h*8 + j)*DD + d);
                c1h += __ldg(g_T8e + (size_t)(t8base + sc_h*8 + j)*DD + d);
            }
            if (j < r_l) {
                c0l += __ldg(g_T8  + (size_t)(t8base + sc_l*8 + j)*DD + d);
                c1l += __ldg(g_T8e + (size_t)(t8base + sc_l*8 + j)*DD + d);
            }
        }

        float xh[8], eh[8], xl[8], el[8], Ar[8], Er[8];
#pragma unroll
        for (int i = 0; i < 8; i++) {
            int th = min(t0 + 64 + i, LL - 1);
            int tl = max(t0 - 64 + i, 0);
            xh[i] = __ldg(xb + (size_t)th*DD + d);
            xl[i] = __ldg(xb + (size_t)tl*DD + d);
            eh[i] = __ldg(ekb + th) * whi;
            el[i] = __ldg(ekb + tl) * wlo;
            Ar[i] = __ldg(g_A + b*LL + t0 + i);
            Er[i] = __ldg(g_E + b*LL + t0 + i);
        }

        float V0 = c0h - c0l;
        float V1 = c1h - c1l;
        float* ob = out + ((size_t)b*LL + t0)*DD + d;

#pragma unroll
        for (int i = 0; i < 8; i++) {
            V0 = fmaf( whi, xh[i], V0);
            V1 = fmaf(eh[i], xh[i], V1);
            V0 = fmaf(-wlo, xl[i], V0);
            V1 = fmaf(-el[i], xl[i], V1);
            ob[(size_t)i*DD] = Ar[i]*V1 + Er[i]*(tot - V0);
        }
    }

    // ---- reset barrier state for next (graph-replayed) launch ----
    if (threadIdx.x == 0) {
        unsigned old = atomicAdd(&g_done, 1u);
        if (old == GRID - 1) {      // last block: everyone passed both barriers
            g_cnt  = 0u;
            g_done = 0u;
            __threadfence();
        }
    }
}

extern "C" void kernel_launch(void* const* d_in, const int* in_sizes, int n_in,
                              void* d_out, int out_size) {
    const float* x  = (const float*)d_in[0];   // [B,L,D]
    const float* Wt = (const float*)d_in[1];   // [D,U]
    const float* Wx = (const float*)d_in[2];   // [D,U]
    const float* bh = (const float*)d_in[3];   // [U]
    const float* Wa = (const float*)d_in[4];   // [U,1]
    const float* ba = (const float*)d_in[5];   // [1]
    float* out = (float*)d_out;                // [B,L,D]

    fused<<<GRID, 256>>>(x, Wt, Wx, bh, Wa, ba, out);
}

// round 13
// speedup vs baseline: 1.2786x; 1.2786x over previous
#include <cuda_runtime.h>
#include <math.h>

#define BB 8
#define LL 512
#define DD 128
#define UU 32
#define EPSF 1e-7f
#define NC 64            // 8-row chunks per batch
#define NSC 8            // superchunks of 64 rows per batch

// scratch (no allocs allowed)
__device__ float g_qs[BB*LL];
__device__ float g_ks[BB*LL];
__device__ float g_ek[BB*LL];
__device__ float g_T8 [BB*NC*DD];       // 8-row sums of x
__device__ float g_T8e[BB*NC*DD];       // 8-row sums of ek*x
__device__ float g_SO0[BB*(NSC+1)*DD];  // exclusive superchunk offsets of x; [8]=total
__device__ float g_SO1[BB*(NSC+1)*DD];  // exclusive superchunk offsets of ek*x
__device__ float g_A[BB*LL];            // exp(qc-m)/Z
__device__ float g_E[BB*LL];            // exp(-m)/Z

// ---------------------------------------------------------------------------
// K1: register weight fold (width-8 shfl reduce) + warp-per-token scalars +
//     chunk-8 sums. grid=512, blk=256
// ---------------------------------------------------------------------------
__global__ __launch_bounds__(256)
void k1(const float* __restrict__ x,
        const float* __restrict__ Wt, const float* __restrict__ Wx,
        const float* __restrict__ Wa) {
    int tid  = threadIdx.x;
    int warp = tid >> 5;
    int lane = tid & 31;
    int token = blockIdx.x * 8 + warp;          // 8 consecutive rows, same batch

    __shared__ __align__(16) float swt[DD], swx[DD];
    __shared__ __align__(16) float srow[8*DD];
    __shared__ float sek[8];

    // issue x load first (long latency, overlaps fold)
    const float4* xr = reinterpret_cast<const float4*>(x + (size_t)token * DD);
    float4 xv = xr[lane];
    reinterpret_cast<float4*>(srow)[warp*32 + lane] = xv;

    // fold with zero smem staging:
    // thread's u-group is fixed: ug = tid&7; row(i) = (tid + 256*i) >> 3.
    {
        int ug = tid & 7;
        float4 wa = reinterpret_cast<const float4*>(Wa)[ug];
        const float4* Wt4 = reinterpret_cast<const float4*>(Wt);
        const float4* Wx4 = reinterpret_cast<const float4*>(Wx);
#pragma unroll
        for (int i = 0; i < 4; i++) {
            int idx = tid + i*256;
            int row = idx >> 3;
            float4 vt = __ldg(Wt4 + idx);
            float4 vx = __ldg(Wx4 + idx);
            float pt = vt.x*wa.x + vt.y*wa.y + vt.z*wa.z + vt.w*wa.w;
            float px = vx.x*wa.x + vx.y*wa.y + vx.z*wa.z + vx.w*wa.w;
#pragma unroll
            for (int o = 4; o; o >>= 1) {       // reduce across 8-lane row group
                pt += __shfl_down_sync(0xFFFFFFFFu, pt, o, 8);
                px += __shfl_down_sync(0xFFFFFFFFu, px, o, 8);
            }
            if (ug == 0) { swt[row] = pt; swx[row] = px; }
        }
    }
    __syncthreads();

    float4 wt = reinterpret_cast<const float4*>(swt)[lane];
    float4 wx = reinterpret_cast<const float4*>(swx)[lane];
    float q = xv.x*wt.x + xv.y*wt.y + xv.z*wt.z + xv.w*wt.w;
    float k = xv.x*wx.x + xv.y*wx.y + xv.z*wx.z + xv.w*wx.w;
#pragma unroll
    for (int o = 16; o; o >>= 1) {
        q += __shfl_down_sync(0xFFFFFFFFu, q, o);
        k += __shfl_down_sync(0xFFFFFFFFu, k, o);
    }
    if (lane == 0) {
        float e = expf(k);
        g_qs[token] = q;
        g_ks[token] = k;
        g_ek[token] = e;
        sek[warp] = e;
    }
    __syncthreads();

    if (tid < DD) {
        int d = tid;
        float s0 = 0.f, s1 = 0.f;
#pragma unroll
        for (int w = 0; w < 8; w++) {
            float v = srow[w*DD + d];
            s0 += v;
            s1 = fmaf(sek[w], v, s1);
        }
        size_t o = (size_t)blockIdx.x * DD + d;
        g_T8 [o] = s0;
        g_T8e[o] = s1;
    }
}

// ---------------------------------------------------------------------------
// K2: per-batch: scan(ek) + window max + A/E scalars + superchunk offsets SO.
//     grid=8, blk=512
// ---------------------------------------------------------------------------
__global__ __launch_bounds__(512, 1)
void k2(const float* __restrict__ bh, const float* __restrict__ Wa,
        const float* __restrict__ ba) {
    int b   = blockIdx.x;
    int tid = threadIdx.x;

    __shared__ float sks[LL];
    __shared__ float scan[2][LL];
    __shared__ float cmax[LL/16];
    __shared__ float s8[2][NSC][DD];
    __shared__ float sc_c;

    sks[tid]     = g_ks[b*LL + tid];
    scan[0][tid] = g_ek[b*LL + tid];
    if (tid == 0) {
        float c = __ldg(ba);
#pragma unroll
        for (int u = 0; u < UU; u++) c = fmaf(__ldg(bh + u), __ldg(Wa + u), c);
        sc_c = c;
    }
    __syncthreads();

    if (tid < LL/16) {
        float m = sks[tid*16];
#pragma unroll
        for (int i = 1; i < 16; i++) m = fmaxf(m, sks[tid*16 + i]);
        cmax[tid] = m;
    }

    // superchunk sums from T8
    {
        int g = tid >> 7, d = tid & (DD-1);
#pragma unroll
        for (int q = g; q < NSC; q += 4) {
            float a0 = 0.f, a1 = 0.f;
#pragma unroll
            for (int j = 0; j < 8; j++) {
                a0 += g_T8 [(size_t)(b*NC + q*8 + j)*DD + d];
                a1 += g_T8e[(size_t)(b*NC + q*8 + j)*DD + d];
            }
            s8[0][q][d] = a0;
            s8[1][q][d] = a1;
        }
    }

    // Hillis-Steele inclusive scan of ek (9 steps)
    int cur = 0;
#pragma unroll
    for (int off = 1; off < LL; off <<= 1) {
        __syncthreads();
        float v = scan[cur][tid];
        if (tid >= off) v += scan[cur][tid - off];
        scan[cur ^ 1][tid] = v;
        cur ^= 1;
    }
    __syncthreads();

    // exclusive superchunk offsets (incl. total at [8]) -> global
    if (tid < DD) {
        int d = tid;
        float r0 = 0.f, r1 = 0.f;
#pragma unroll
        for (int sc = 0; sc < NSC; sc++) {
            g_SO0[(size_t)(b*(NSC+1) + sc)*DD + d] = r0;
            g_SO1[(size_t)(b*(NSC+1) + sc)*DD + d] = r1;
            r0 += s8[0][sc][d];
            r1 += s8[1][sc][d];
        }
        g_SO0[(size_t)(b*(NSC+1) + NSC)*DD + d] = r0;
        g_SO1[(size_t)(b*(NSC+1) + NSC)*DD + d] = r1;
    }

    // per-query softmax scalars
    {
        int t  = tid;
        int lo = max(0, t - 63);
        int hi = min(LL - 1, t + 64);
        int wc = hi - lo + 1;

        float wm = -INFINITY;
        int c0 = lo >> 4, c1 = hi >> 4;
        int e0 = (c0 + 1) << 4;
        for (int s = lo; s < e0; s++) wm = fmaxf(wm, sks[s]);
        for (int c = c0 + 1; c < c1; c++) wm = fmaxf(wm, cmax[c]);
        for (int s = c1 << 4; s <= hi; s++) wm = fmaxf(wm, sks[s]);

        float qc = g_qs[b*LL + t] + sc_c;
        float m  = fmaxf(0.f, qc + wm);     // masked entries score 0, always present
        float A  = expf(qc - m);
        float E  = expf(-m);
        float S1 = scan[cur][hi] - (lo > 0 ? scan[cur][lo-1] : 0.f);
        float Z  = A * S1 + E * (float)(LL - wc) + EPSF;
        float iv = 1.f / Z;
        g_A[b*LL + t] = A * iv;
        g_E[b*LL + t] = E * iv;
    }
}

// ---------------------------------------------------------------------------
// K3f: fused window-sum + output, fully preloaded; 4 queries/block with an
//      8-aligned anchor t8 (masked pre-slides). grid=1024, blk=128
// ---------------------------------------------------------------------------
__global__ __launch_bounds__(128)
void k3f(const float* __restrict__ x, float* __restrict__ out) {
    int blk = blockIdx.x;                // 0..1023
    int b   = blk >> 7;
    int t0  = (blk & 127) * 4;           // first query of this block
    int t8  = t0 & ~7;                   // 8-aligned anchor
    int pre = t0 - t8;                   // 0 or 4 pre-slides
    int d   = threadIdx.x;

    bool lo_act = (t8 >= 64);    // else window bottom pinned at 0 for t8..t8+7
    bool hi_act = (t8 <= 440);   // else window top pinned at 511 for t8..t8+7
    float whi = hi_act ? 1.f : 0.f;
    float wlo = lo_act ? 1.f : 0.f;

    int jh = hi_act ? ((t8 >> 3) + 8) : NC;   // chunk index of anchor window top
    int jl = lo_act ? ((t8 >> 3) - 8) : 0;    // chunk index of anchor window bottom
    int sc_h = jh >> 3, r_h = jh & 7;
    int sc_l = jl >> 3, r_l = jl & 7;

    const float* xb  = x + (size_t)b * LL * DD;
    const float* ekb = g_ek + b*LL;
    size_t sobase = (size_t)b * (NSC+1) * DD;
    size_t t8base = (size_t)b * NC;

    // ---- issue ALL loads up front (independent; predicated T8 hops) ----
    float c0h = __ldg(g_SO0 + sobase + (size_t)sc_h*DD + d);
    float c1h = __ldg(g_SO1 + sobase + (size_t)sc_h*DD + d);
    float c0l = __ldg(g_SO0 + sobase + (size_t)sc_l*DD + d);
    float c1l = __ldg(g_SO1 + sobase + (size_t)sc_l*DD + d);
    float tot = __ldg(g_SO0 + sobase + (size_t)NSC*DD + d);

#pragma unroll
    for (int j = 0; j < 7; j++) {
        if (j < r_h) {
            c0h += __ldg(g_T8  + (size_t)(t8base + sc_h*8 + j)*DD + d);
            c1h += __ldg(g_T8e + (size_t)(t8base + sc_h*8 + j)*DD + d);
        }
        if (j < r_l) {
            c0l += __ldg(g_T8  + (size_t)(t8base + sc_l*8 + j)*DD + d);
            c1l += __ldg(g_T8e + (size_t)(t8base + sc_l*8 + j)*DD + d);
        }
    }

    float xh[8], eh[8], xl[8], el[8], Ar[4], Er[4];
#pragma unroll
    for (int i = 0; i < 8; i++) {
        int th = min(t8 + 64 + i, LL - 1);          // clamped: always valid
        int tl = max(t8 - 64 + i, 0);
        xh[i] = __ldg(xb + (size_t)th*DD + d);
        xl[i] = __ldg(xb + (size_t)tl*DD + d);
        eh[i] = __ldg(ekb + th) * whi;              // masked weight
        el[i] = __ldg(ekb + tl) * wlo;
    }
#pragma unroll
    for (int i = 0; i < 4; i++) {
        Ar[i] = __ldg(g_A + b*LL + t0 + i);
        Er[i] = __ldg(g_E + b*LL + t0 + i);
    }

    // ---- pure register compute: slide from anchor, emit queries t0..t0+3 ----
    float V0 = c0h - c0l;
    float V1 = c1h - c1l;
    float* ob = out + ((size_t)b*LL + t0)*DD + d;

    if (pre == 0) {
#pragma unroll
        for (int i = 0; i < 4; i++) {
            V0 = fmaf( whi, xh[i], V0);
            V1 = fmaf(eh[i], xh[i], V1);
            V0 = fmaf(-wlo, xl[i], V0);
            V1 = fmaf(-el[i], xl[i], V1);
            ob[(size_t)i*DD] = Ar[i]*V1 + Er[i]*(tot - V0);
        }
    } else {
#pragma unroll
        for (int i = 0; i < 8; i++) {
            V0 = fmaf( whi, xh[i], V0);
            V1 = fmaf(eh[i], xh[i], V1);
            V0 = fmaf(-wlo, xl[i], V0);
            V1 = fmaf(-el[i], xl[i], V1);
            if (i >= 4)
                ob[(size_t)(i-4)*DD] = Ar[i-4]*V1 + Er[i-4]*(tot - V0);
        }
    }
}

extern "C" void kernel_launch(void* const* d_in, const int* in_sizes, int n_in,
                              void* d_out, int out_size) {
    const float* x  = (const float*)d_in[0];   // [B,L,D]
    const float* Wt = (const float*)d_in[1];   // [D,U]
    const float* Wx = (const float*)d_in[2];   // [D,U]
    const float* bh = (const float*)d_in[3];   // [U]
    const float* Wa = (const float*)d_in[4];   // [U,1]
    const float* ba = (const float*)d_in[5];   // [1]
    float* out = (float*)d_out;                // [B,L,D]

    k1<<<BB*LL/8, 256>>>(x, Wt, Wx, Wa);
    k2<<<BB, 512>>>(bh, Wa, ba);
    k3f<<<BB*LL/4, DD>>>(x, out);
}